// round 8
// baseline (speedup 1.0000x reference)
#include <cuda_runtime.h>
#include <cuda_bf16.h>
#include <cstdint>

#define DK 64
#define HN 256
#define TILE_M 128
#define THREADS 256

// precomputed centers (bf16 hi/lo packed pairs) + {c2*log2e, w}
__device__ uint32_t g_Chi[HN * DK / 2];
__device__ uint32_t g_Clo[HN * DK / 2];
__device__ float2   g_cw[HN];

// ---- smem byte offsets from 1024-aligned base ----
#define OFF_BHI 0          // 256x128B bf16-hi centers, swizzled
#define OFF_BLO 32768      // 256x128B bf16-lo centers
#define OFF_AHI 65536      // 128x128B X-hi
#define OFF_ALO 81920      // 128x128B X-lo
#define OFF_CW  98304      // float2[256]
#define OFF_X2  100352     // float[128]  (x2 * log2e)
#define OFF_RED 100864     // float[128][2]
#define SMEM_SZ (101888 + 1024)

#define LOG2E 1.4426950408889634f

static __device__ __forceinline__ uint32_t smem_u32(const void* p) {
    uint32_t a;
    asm("{ .reg .u64 t; cvta.to.shared.u64 t, %1; cvt.u32.u64 %0, t; }" : "=r"(a) : "l"(p));
    return a;
}
static __device__ __forceinline__ float ex2_approx(float x) {
    float r; asm("ex2.approx.f32 %0, %1;" : "=f"(r) : "f"(x)); return r;
}

#define LDSM_X4(r0, r1, r2, r3, addr) \
    asm volatile("ldmatrix.sync.aligned.m8n8.x4.shared.b16 {%0,%1,%2,%3}, [%4];" \
        : "=r"(r0), "=r"(r1), "=r"(r2), "=r"(r3) : "r"(addr))

static __device__ __forceinline__ void mma_bf16(float* c, const uint32_t* a,
                                                uint32_t b0, uint32_t b1) {
    asm volatile(
        "mma.sync.aligned.m16n8k16.row.col.f32.bf16.bf16.f32 "
        "{%0,%1,%2,%3}, {%4,%5,%6,%7}, {%8,%9}, {%0,%1,%2,%3};"
        : "+f"(c[0]), "+f"(c[1]), "+f"(c[2]), "+f"(c[3])
        : "r"(a[0]), "r"(a[1]), "r"(a[2]), "r"(a[3]), "r"(b0), "r"(b1));
}

// split 2 fp32 into packed bf16 hi/lo pairs; accumulate squared norm
static __device__ __forceinline__ void cvt_pair(float a, float b, uint32_t& hi,
                                                uint32_t& lo, float& s2) {
    s2 = fmaf(a, a, s2); s2 = fmaf(b, b, s2);
    __nv_bfloat16 ha = __float2bfloat16_rn(a), hb = __float2bfloat16_rn(b);
    float ra = a - __bfloat162float(ha), rb = b - __bfloat162float(hb);
    __nv_bfloat16 la = __float2bfloat16_rn(ra), lb = __float2bfloat16_rn(rb);
    hi = (uint32_t)__bfloat16_as_ushort(ha) | ((uint32_t)__bfloat16_as_ushort(hb) << 16);
    lo = (uint32_t)__bfloat16_as_ushort(la) | ((uint32_t)__bfloat16_as_ushort(lb) << 16);
}

__global__ void prep_kernel(const float* __restrict__ C, const float* __restrict__ W) {
    const int h = threadIdx.x;              // 256 threads, 1 block
    const float4* cp = (const float4*)(C + h * DK);
    float c2 = 0.f;
    #pragma unroll
    for (int q = 0; q < 16; q++) {
        float4 v = cp[q];
        uint32_t h0, l0, h1, l1;
        cvt_pair(v.x, v.y, h0, l0, c2);
        cvt_pair(v.z, v.w, h1, l1, c2);
        g_Chi[h * 32 + q * 2]     = h0;
        g_Chi[h * 32 + q * 2 + 1] = h1;
        g_Clo[h * 32 + q * 2]     = l0;
        g_Clo[h * 32 + q * 2 + 1] = l1;
    }
    g_cw[h] = make_float2(c2 * LOG2E, W[h]);
}

__global__ void __launch_bounds__(THREADS, 2)
rbf_mma_kernel(const float* __restrict__ X, const float* __restrict__ Bias,
               float* __restrict__ out, int ntiles) {
    extern __shared__ char smem_raw[];
    uint32_t sraw = smem_u32(smem_raw);
    uint32_t sb = (sraw + 1023u) & ~1023u;
    char* sc = smem_raw + (sb - sraw);

    const int tid = threadIdx.x;
    const int warp = tid >> 5, lane = tid & 31;
    const int wm = warp >> 1, wn = warp & 1;          // 4 M-warps x 2 N-warps
    const int g = lane >> 2, qq = lane & 3;
    const float TWO_LOG2E = 2.0f * LOG2E;
    const float b0 = Bias[0];

    float*  x2s  = (float*)(sc + OFF_X2);
    float2* cws  = (float2*)(sc + OFF_CW);
    float*  red  = (float*)(sc + OFF_RED);

    // ---- stage centers (one thread per center row), swizzled chunks ----
    {
        const int h = tid;
        const uint4* hp = (const uint4*)g_Chi + h * 8;
        const uint4* lp = (const uint4*)g_Clo + h * 8;
        #pragma unroll
        for (int q = 0; q < 8; q++) {
            int co = ((q ^ (h & 7)) * 16);
            *(uint4*)(sc + OFF_BHI + h * 128 + co) = hp[q];
            *(uint4*)(sc + OFF_BLO + h * 128 + co) = lp[q];
        }
        cws[h] = g_cw[h];
    }

    // ---- tile-invariant ldmatrix base addresses (kt folds in as XOR of kt<<5) ----
    const int roff = (lane & 7) + ((lane >> 3) & 1) * 8;
    const int s16 = lane >> 4;
    uint32_t aAhi[2], aAlo[2], aBhi[2], aBlo[2];
    #pragma unroll
    for (int mt = 0; mt < 2; mt++) {
        int r = wm * 32 + mt * 16 + roff;
        uint32_t t16 = (uint32_t)((s16 ^ (r & 7)) * 16);
        aAhi[mt] = sb + OFF_AHI + r * 128 + t16;
        aAlo[mt] = sb + OFF_ALO + r * 128 + t16;
    }
    #pragma unroll
    for (int gg = 0; gg < 2; gg++) {
        int n = wn * 32 + gg * 16 + roff;
        uint32_t t16 = (uint32_t)((s16 ^ (n & 7)) * 16);
        aBhi[gg] = sb + OFF_BHI + n * 128 + t16;
        aBlo[gg] = sb + OFF_BLO + n * 128 + t16;
    }

    for (int t = blockIdx.x; t < ntiles; t += gridDim.x) {
        // ---- stage X tile: thread = half a row ----
        {
            const int row = tid >> 1, half = tid & 1;
            const float4* xp = (const float4*)(X + ((size_t)t * TILE_M + row) * DK + half * 32);
            float s2 = 0.f;
            char* ah = sc + OFF_AHI + row * 128;
            char* al = sc + OFF_ALO + row * 128;
            #pragma unroll
            for (int q = 0; q < 4; q++) {
                float4 v0 = xp[2 * q], v1 = xp[2 * q + 1];
                uint32_t h0, l0, h1, l1, h2, l2, h3, l3;
                cvt_pair(v0.x, v0.y, h0, l0, s2);
                cvt_pair(v0.z, v0.w, h1, l1, s2);
                cvt_pair(v1.x, v1.y, h2, l2, s2);
                cvt_pair(v1.z, v1.w, h3, l3, s2);
                int c = half * 4 + q;
                int co = ((c ^ (row & 7)) * 16);
                *(uint4*)(ah + co) = make_uint4(h0, h1, h2, h3);
                *(uint4*)(al + co) = make_uint4(l0, l1, l2, l3);
            }
            s2 += __shfl_xor_sync(0xffffffffu, s2, 1);
            if (!half) x2s[row] = s2 * LOG2E;
        }
        __syncthreads();

        float rowsum[2][2] = {{0.f, 0.f}, {0.f, 0.f}};   // [mt][row-group]

        #pragma unroll 1
        for (int nc = 0; nc < 4; nc++) {                 // N chunks of 64
            const int hbase = nc * 64 + wn * 32;
            const uint32_t bo = (uint32_t)(nc * 64 * 128);   // +64 center rows
            float acc[2][4][4];
            #pragma unroll
            for (int mt = 0; mt < 2; mt++)
                #pragma unroll
                for (int nt = 0; nt < 4; nt++)
                    #pragma unroll
                    for (int k = 0; k < 4; k++) acc[mt][nt][k] = 0.f;

            // fused K loop: load each fragment ONCE, issue all 3 bf16-split
            // products (hi*hi + lo*hi + hi*lo) into the same accumulators
            #pragma unroll
            for (int kt = 0; kt < 4; kt++) {
                const uint32_t kx = (uint32_t)(kt << 5);
                uint32_t ah[2][4], al[2][4], bh[2][4], bl[2][4];
                #pragma unroll
                for (int mt = 0; mt < 2; mt++) {
                    LDSM_X4(ah[mt][0], ah[mt][1], ah[mt][2], ah[mt][3], aAhi[mt] ^ kx);
                    LDSM_X4(al[mt][0], al[mt][1], al[mt][2], al[mt][3], aAlo[mt] ^ kx);
                }
                #pragma unroll
                for (int gg = 0; gg < 2; gg++) {
                    LDSM_X4(bh[gg][0], bh[gg][1], bh[gg][2], bh[gg][3], (aBhi[gg] + bo) ^ kx);
                    LDSM_X4(bl[gg][0], bl[gg][1], bl[gg][2], bl[gg][3], (aBlo[gg] + bo) ^ kx);
                }
                #pragma unroll
                for (int mt = 0; mt < 2; mt++)
                    #pragma unroll
                    for (int nt = 0; nt < 4; nt++) {
                        const int gg = nt >> 1, od = nt & 1;
                        mma_bf16(acc[mt][nt], ah[mt], bh[gg][od], bh[gg][od + 2]);
                        mma_bf16(acc[mt][nt], al[mt], bh[gg][od], bh[gg][od + 2]);
                        mma_bf16(acc[mt][nt], ah[mt], bl[gg][od], bl[gg][od + 2]);
                    }
            }

            // ---- epilogue for this chunk ----
            #pragma unroll
            for (int mt = 0; mt < 2; mt++) {
                const float nx0 = -x2s[wm * 32 + mt * 16 + g];
                const float nx1 = -x2s[wm * 32 + mt * 16 + 8 + g];
                #pragma unroll
                for (int nt = 0; nt < 4; nt++) {
                    const int h = hbase + nt * 8 + qq * 2;
                    const float2 cw0 = cws[h];
                    const float2 cw1 = cws[h + 1];
                    float t00 = fminf(fmaf(acc[mt][nt][0], TWO_LOG2E, nx0 - cw0.x), 0.f);
                    float t01 = fminf(fmaf(acc[mt][nt][1], TWO_LOG2E, nx0 - cw1.x), 0.f);
                    float t10 = fminf(fmaf(acc[mt][nt][2], TWO_LOG2E, nx1 - cw0.x), 0.f);
                    float t11 = fminf(fmaf(acc[mt][nt][3], TWO_LOG2E, nx1 - cw1.x), 0.f);
                    rowsum[mt][0] = fmaf(cw0.y, ex2_approx(t00), rowsum[mt][0]);
                    rowsum[mt][0] = fmaf(cw1.y, ex2_approx(t01), rowsum[mt][0]);
                    rowsum[mt][1] = fmaf(cw0.y, ex2_approx(t10), rowsum[mt][1]);
                    rowsum[mt][1] = fmaf(cw1.y, ex2_approx(t11), rowsum[mt][1]);
                }
            }
        }

        // ---- reduce 4 col-lanes, then the 2 N-warps via smem ----
        #pragma unroll
        for (int mt = 0; mt < 2; mt++)
            #pragma unroll
            for (int rg = 0; rg < 2; rg++) {
                float v = rowsum[mt][rg];
                v += __shfl_xor_sync(0xffffffffu, v, 1);
                v += __shfl_xor_sync(0xffffffffu, v, 2);
                if (qq == 0)
                    red[(wm * 32 + mt * 16 + rg * 8 + g) * 2 + wn] = v;
            }
        __syncthreads();
        if (tid < TILE_M)
            out[(size_t)t * TILE_M + tid] = red[tid * 2] + red[tid * 2 + 1] + b0;
    }
}

extern "C" void kernel_launch(void* const* d_in, const int* in_sizes, int n_in,
                              void* d_out, int out_size) {
    const float* X = (const float*)d_in[0];
    const float* C = (const float*)d_in[1];
    const float* w = (const float*)d_in[2];
    const float* b = (const float*)d_in[3];
    float* out = (float*)d_out;

    const int ntiles = in_sizes[0] / (DK * TILE_M);   // 4096
    int dev = 0, sms = 148;
    cudaGetDevice(&dev);
    cudaDeviceGetAttribute(&sms, cudaDevAttrMultiProcessorCount, dev);
    int grid = 2 * sms;
    if (grid > ntiles) grid = ntiles;

    prep_kernel<<<1, HN>>>(C, w);
    cudaFuncSetAttribute(rbf_mma_kernel,
                         cudaFuncAttributeMaxDynamicSharedMemorySize, SMEM_SZ);
    rbf_mma_kernel<<<grid, THREADS, SMEM_SZ>>>(X, b, out, ntiles);
}

// round 10
// speedup vs baseline: 1.5223x; 1.5223x over previous
#include <cuda_runtime.h>
#include <cuda_bf16.h>
#include <cstdint>

#define DK 64
#define HN 256
#define TILE_M 128
#define THREADS 256

// precomputed centers (bf16 hi/lo packed pairs) + {c2*log2e, w}
__device__ uint32_t g_Chi[HN * DK / 2];
__device__ uint32_t g_Clo[HN * DK / 2];
__device__ float2   g_cw[HN];

// ---- smem byte offsets from 1024-aligned base ----
#define OFF_BHI 0          // 256x128B bf16-hi centers, swizzled
#define OFF_BLO 32768      // 256x128B bf16-lo centers
#define OFF_AHI 65536      // 128x128B X-hi
#define OFF_ALO 81920      // 128x128B X-lo
#define OFF_CW  98304      // float2[256]
#define OFF_X2  100352     // float[128]  (x2 * log2e)
#define OFF_RED 100864     // float[128][2]
#define SMEM_SZ (101888 + 1024)

#define LOG2E 1.4426950408889634f

static __device__ __forceinline__ uint32_t smem_u32(const void* p) {
    uint32_t a;
    asm("{ .reg .u64 t; cvta.to.shared.u64 t, %1; cvt.u32.u64 %0, t; }" : "=r"(a) : "l"(p));
    return a;
}
static __device__ __forceinline__ float ex2_approx(float x) {
    float r; asm("ex2.approx.f32 %0, %1;" : "=f"(r) : "f"(x)); return r;
}

#define LDSM_X4(r0, r1, r2, r3, addr) \
    asm volatile("ldmatrix.sync.aligned.m8n8.x4.shared.b16 {%0,%1,%2,%3}, [%4];" \
        : "=r"(r0), "=r"(r1), "=r"(r2), "=r"(r3) : "r"(addr))

static __device__ __forceinline__ void mma_bf16(float* c, const uint32_t* a,
                                                uint32_t b0, uint32_t b1) {
    asm volatile(
        "mma.sync.aligned.m16n8k16.row.col.f32.bf16.bf16.f32 "
        "{%0,%1,%2,%3}, {%4,%5,%6,%7}, {%8,%9}, {%0,%1,%2,%3};"
        : "+f"(c[0]), "+f"(c[1]), "+f"(c[2]), "+f"(c[3])
        : "r"(a[0]), "r"(a[1]), "r"(a[2]), "r"(a[3]), "r"(b0), "r"(b1));
}

// split 2 fp32 into packed bf16 hi/lo pairs; accumulate squared norm
static __device__ __forceinline__ void cvt_pair(float a, float b, uint32_t& hi,
                                                uint32_t& lo, float& s2) {
    s2 = fmaf(a, a, s2); s2 = fmaf(b, b, s2);
    __nv_bfloat16 ha = __float2bfloat16_rn(a), hb = __float2bfloat16_rn(b);
    float ra = a - __bfloat162float(ha), rb = b - __bfloat162float(hb);
    __nv_bfloat16 la = __float2bfloat16_rn(ra), lb = __float2bfloat16_rn(rb);
    hi = (uint32_t)__bfloat16_as_ushort(ha) | ((uint32_t)__bfloat16_as_ushort(hb) << 16);
    lo = (uint32_t)__bfloat16_as_ushort(la) | ((uint32_t)__bfloat16_as_ushort(lb) << 16);
}

__global__ void prep_kernel(const float* __restrict__ C, const float* __restrict__ W) {
    const int h = threadIdx.x;              // 256 threads, 1 block
    const float4* cp = (const float4*)(C + h * DK);
    float c2 = 0.f;
    #pragma unroll
    for (int q = 0; q < 16; q++) {
        float4 v = cp[q];
        uint32_t h0, l0, h1, l1;
        cvt_pair(v.x, v.y, h0, l0, c2);
        cvt_pair(v.z, v.w, h1, l1, c2);
        g_Chi[h * 32 + q * 2]     = h0;
        g_Chi[h * 32 + q * 2 + 1] = h1;
        g_Clo[h * 32 + q * 2]     = l0;
        g_Clo[h * 32 + q * 2 + 1] = l1;
    }
    g_cw[h] = make_float2(c2 * LOG2E, W[h]);
}

__global__ void __launch_bounds__(THREADS, 2)
rbf_mma_kernel(const float* __restrict__ X, const float* __restrict__ Bias,
               float* __restrict__ out, int ntiles) {
    extern __shared__ char smem_raw[];
    uint32_t sraw = smem_u32(smem_raw);
    uint32_t sb = (sraw + 1023u) & ~1023u;
    char* sc = smem_raw + (sb - sraw);

    const int tid = threadIdx.x;
    const int warp = tid >> 5, lane = tid & 31;
    const int wm = warp >> 1, wn = warp & 1;          // 4 M-warps x 2 N-warps
    const int g = lane >> 2, qq = lane & 3;
    const float TWO_LOG2E = 2.0f * LOG2E;
    const float b0 = Bias[0];

    float*  x2s  = (float*)(sc + OFF_X2);
    float2* cws  = (float2*)(sc + OFF_CW);
    float*  red  = (float*)(sc + OFF_RED);

    // ---- stage centers (one thread per center row), swizzled chunks ----
    {
        const int h = tid;
        const uint4* hp = (const uint4*)g_Chi + h * 8;
        const uint4* lp = (const uint4*)g_Clo + h * 8;
        #pragma unroll
        for (int q = 0; q < 8; q++) {
            int co = ((q ^ (h & 7)) * 16);
            *(uint4*)(sc + OFF_BHI + h * 128 + co) = hp[q];
            *(uint4*)(sc + OFF_BLO + h * 128 + co) = lp[q];
        }
        cws[h] = g_cw[h];
    }

    // ---- tile-invariant ldmatrix base addresses (kt folds in as XOR of kt<<5) ----
    const int roff = (lane & 7) + ((lane >> 3) & 1) * 8;
    const int s16 = lane >> 4;
    uint32_t aAhi[2], aAlo[2], aBhi[2], aBlo[2];
    #pragma unroll
    for (int mt = 0; mt < 2; mt++) {
        int r = wm * 32 + mt * 16 + roff;
        uint32_t t16 = (uint32_t)((s16 ^ (r & 7)) * 16);
        aAhi[mt] = sb + OFF_AHI + r * 128 + t16;
        aAlo[mt] = sb + OFF_ALO + r * 128 + t16;
    }
    #pragma unroll
    for (int gg = 0; gg < 2; gg++) {
        int n = wn * 32 + gg * 16 + roff;
        uint32_t t16 = (uint32_t)((s16 ^ (n & 7)) * 16);
        aBhi[gg] = sb + OFF_BHI + n * 128 + t16;
        aBlo[gg] = sb + OFF_BLO + n * 128 + t16;
    }

    for (int t = blockIdx.x; t < ntiles; t += gridDim.x) {
        // ---- stage X tile: thread = half a row ----
        {
            const int row = tid >> 1, half = tid & 1;
            const float4* xp = (const float4*)(X + ((size_t)t * TILE_M + row) * DK + half * 32);
            float s2 = 0.f;
            char* ah = sc + OFF_AHI + row * 128;
            char* al = sc + OFF_ALO + row * 128;
            #pragma unroll
            for (int q = 0; q < 4; q++) {
                float4 v0 = xp[2 * q], v1 = xp[2 * q + 1];
                uint32_t h0, l0, h1, l1, h2, l2, h3, l3;
                cvt_pair(v0.x, v0.y, h0, l0, s2);
                cvt_pair(v0.z, v0.w, h1, l1, s2);
                cvt_pair(v1.x, v1.y, h2, l2, s2);
                cvt_pair(v1.z, v1.w, h3, l3, s2);
                int c = half * 4 + q;
                int co = ((c ^ (row & 7)) * 16);
                *(uint4*)(ah + co) = make_uint4(h0, h1, h2, h3);
                *(uint4*)(al + co) = make_uint4(l0, l1, l2, l3);
            }
            s2 += __shfl_xor_sync(0xffffffffu, s2, 1);
            if (!half) x2s[row] = s2 * LOG2E;
        }
        __syncthreads();

        float rowsum[2][2] = {{0.f, 0.f}, {0.f, 0.f}};   // [mt][row-group]

        #pragma unroll 1
        for (int nc = 0; nc < 4; nc++) {                 // N chunks of 64
            const int hbase = nc * 64 + wn * 32;
            const uint32_t bo = (uint32_t)(nc * 64 * 128);   // +64 center rows
            const uint32_t bBh0 = aBhi[0] + bo, bBh1 = aBhi[1] + bo;
            const uint32_t bBl0 = aBlo[0] + bo, bBl1 = aBlo[1] + bo;

            float acc[2][4][4];
            #pragma unroll
            for (int mt = 0; mt < 2; mt++)
                #pragma unroll
                for (int nt = 0; nt < 4; nt++)
                    #pragma unroll
                    for (int k = 0; k < 4; k++) acc[mt][nt][k] = 0.f;

            // fused K loop, shallow-queue schedule: never more than 2 LDSM
            // in flight before consuming MMAs are issued.
            #pragma unroll
            for (int kt = 0; kt < 4; kt++) {
                const uint32_t kx = (uint32_t)(kt << 5);
                uint32_t ah[2][4], al[2][4], bh[2][4], bl[2][4];

                // -- B-hi + A-hi, then hi*hi --
                LDSM_X4(bh[0][0], bh[0][1], bh[0][2], bh[0][3], bBh0 ^ kx);
                LDSM_X4(bh[1][0], bh[1][1], bh[1][2], bh[1][3], bBh1 ^ kx);
                LDSM_X4(ah[0][0], ah[0][1], ah[0][2], ah[0][3], aAhi[0] ^ kx);
                LDSM_X4(ah[1][0], ah[1][1], ah[1][2], ah[1][3], aAhi[1] ^ kx);
                #pragma unroll
                for (int mt = 0; mt < 2; mt++)
                    #pragma unroll
                    for (int nt = 0; nt < 4; nt++) {
                        const int gg = nt >> 1, od = nt & 1;
                        mma_bf16(acc[mt][nt], ah[mt], bh[gg][od], bh[gg][od + 2]);
                    }

                // -- A-lo, then lo*hi (B-hi still live) --
                LDSM_X4(al[0][0], al[0][1], al[0][2], al[0][3], aAlo[0] ^ kx);
                LDSM_X4(al[1][0], al[1][1], al[1][2], al[1][3], aAlo[1] ^ kx);
                #pragma unroll
                for (int mt = 0; mt < 2; mt++)
                    #pragma unroll
                    for (int nt = 0; nt < 4; nt++) {
                        const int gg = nt >> 1, od = nt & 1;
                        mma_bf16(acc[mt][nt], al[mt], bh[gg][od], bh[gg][od + 2]);
                    }

                // -- B-lo, then hi*lo (A-hi still live) --
                LDSM_X4(bl[0][0], bl[0][1], bl[0][2], bl[0][3], bBl0 ^ kx);
                LDSM_X4(bl[1][0], bl[1][1], bl[1][2], bl[1][3], bBl1 ^ kx);
                #pragma unroll
                for (int mt = 0; mt < 2; mt++)
                    #pragma unroll
                    for (int nt = 0; nt < 4; nt++) {
                        const int gg = nt >> 1, od = nt & 1;
                        mma_bf16(acc[mt][nt], ah[mt], bl[gg][od], bl[gg][od + 2]);
                    }
            }

            // ---- epilogue for this chunk ----
            #pragma unroll
            for (int mt = 0; mt < 2; mt++) {
                const float nx0 = -x2s[wm * 32 + mt * 16 + g];
                const float nx1 = -x2s[wm * 32 + mt * 16 + 8 + g];
                #pragma unroll
                for (int nt = 0; nt < 4; nt++) {
                    const int h = hbase + nt * 8 + qq * 2;
                    const float2 cw0 = cws[h];
                    const float2 cw1 = cws[h + 1];
                    float t00 = fminf(fmaf(acc[mt][nt][0], TWO_LOG2E, nx0 - cw0.x), 0.f);
                    float t01 = fminf(fmaf(acc[mt][nt][1], TWO_LOG2E, nx0 - cw1.x), 0.f);
                    float t10 = fminf(fmaf(acc[mt][nt][2], TWO_LOG2E, nx1 - cw0.x), 0.f);
                    float t11 = fminf(fmaf(acc[mt][nt][3], TWO_LOG2E, nx1 - cw1.x), 0.f);
                    rowsum[mt][0] = fmaf(cw0.y, ex2_approx(t00), rowsum[mt][0]);
                    rowsum[mt][0] = fmaf(cw1.y, ex2_approx(t01), rowsum[mt][0]);
                    rowsum[mt][1] = fmaf(cw0.y, ex2_approx(t10), rowsum[mt][1]);
                    rowsum[mt][1] = fmaf(cw1.y, ex2_approx(t11), rowsum[mt][1]);
                }
            }
        }

        // ---- reduce 4 col-lanes, then the 2 N-warps via smem ----
        #pragma unroll
        for (int mt = 0; mt < 2; mt++)
            #pragma unroll
            for (int rg = 0; rg < 2; rg++) {
                float v = rowsum[mt][rg];
                v += __shfl_xor_sync(0xffffffffu, v, 1);
                v += __shfl_xor_sync(0xffffffffu, v, 2);
                if (qq == 0)
                    red[(wm * 32 + mt * 16 + rg * 8 + g) * 2 + wn] = v;
            }
        __syncthreads();
        if (tid < TILE_M)
            out[(size_t)t * TILE_M + tid] = red[tid * 2] + red[tid * 2 + 1] + b0;
    }
}

extern "C" void kernel_launch(void* const* d_in, const int* in_sizes, int n_in,
                              void* d_out, int out_size) {
    const float* X = (const float*)d_in[0];
    const float* C = (const float*)d_in[1];
    const float* w = (const float*)d_in[2];
    const float* b = (const float*)d_in[3];
    float* out = (float*)d_out;

    const int ntiles = in_sizes[0] / (DK * TILE_M);   // 4096
    int dev = 0, sms = 148;
    cudaGetDevice(&dev);
    cudaDeviceGetAttribute(&sms, cudaDevAttrMultiProcessorCount, dev);
    int grid = 2 * sms;
    if (grid > ntiles) grid = ntiles;

    prep_kernel<<<1, HN>>>(C, w);
    cudaFuncSetAttribute(rbf_mma_kernel,
                         cudaFuncAttributeMaxDynamicSharedMemorySize, SMEM_SZ);
    rbf_mma_kernel<<<grid, THREADS, SMEM_SZ>>>(X, b, out, ntiles);
}

// round 11
// speedup vs baseline: 1.6330x; 1.0727x over previous
#include <cuda_runtime.h>
#include <cuda_bf16.h>
#include <cstdint>

#define DK 64
#define HN 256
#define TILE_M 128
#define THREADS 256

// precomputed centers (bf16 hi/lo packed pairs) + {c2*log2e, w}
__device__ uint32_t g_Chi[HN * DK / 2];
__device__ uint32_t g_Clo[HN * DK / 2];
__device__ float2   g_cw[HN];

// ---- smem byte offsets from 1024-aligned base ----
#define OFF_BHI 0          // 256x128B bf16-hi centers, swizzled
#define OFF_BLO 32768      // 256x128B bf16-lo centers
#define OFF_CW  65536      // float2[256]
#define OFF_RED 67584      // float[128][2]
#define SMEM_SZ (68608 + 1024)

#define LOG2E 1.4426950408889634f

static __device__ __forceinline__ uint32_t smem_u32(const void* p) {
    uint32_t a;
    asm("{ .reg .u64 t; cvta.to.shared.u64 t, %1; cvt.u32.u64 %0, t; }" : "=r"(a) : "l"(p));
    return a;
}
static __device__ __forceinline__ float ex2_approx(float x) {
    float r; asm("ex2.approx.f32 %0, %1;" : "=f"(r) : "f"(x)); return r;
}

#define LDSM_X4(r0, r1, r2, r3, addr) \
    asm volatile("ldmatrix.sync.aligned.m8n8.x4.shared.b16 {%0,%1,%2,%3}, [%4];" \
        : "=r"(r0), "=r"(r1), "=r"(r2), "=r"(r3) : "r"(addr))

static __device__ __forceinline__ void mma_bf16(float* c, const uint32_t* a,
                                                uint32_t b0, uint32_t b1) {
    asm volatile(
        "mma.sync.aligned.m16n8k16.row.col.f32.bf16.bf16.f32 "
        "{%0,%1,%2,%3}, {%4,%5,%6,%7}, {%8,%9}, {%0,%1,%2,%3};"
        : "+f"(c[0]), "+f"(c[1]), "+f"(c[2]), "+f"(c[3])
        : "r"(a[0]), "r"(a[1]), "r"(a[2]), "r"(a[3]), "r"(b0), "r"(b1));
}

// split 2 fp32 into packed bf16 hi/lo pairs; accumulate squared norm
static __device__ __forceinline__ void cvt_pair(float a, float b, uint32_t& hi,
                                                uint32_t& lo, float& s2) {
    s2 = fmaf(a, a, s2); s2 = fmaf(b, b, s2);
    __nv_bfloat16 ha = __float2bfloat16_rn(a), hb = __float2bfloat16_rn(b);
    float ra = a - __bfloat162float(ha), rb = b - __bfloat162float(hb);
    __nv_bfloat16 la = __float2bfloat16_rn(ra), lb = __float2bfloat16_rn(rb);
    hi = (uint32_t)__bfloat16_as_ushort(ha) | ((uint32_t)__bfloat16_as_ushort(hb) << 16);
    lo = (uint32_t)__bfloat16_as_ushort(la) | ((uint32_t)__bfloat16_as_ushort(lb) << 16);
}

__global__ void prep_kernel(const float* __restrict__ C, const float* __restrict__ W) {
    const int h = threadIdx.x;              // 256 threads, 1 block
    const float4* cp = (const float4*)(C + h * DK);
    float c2 = 0.f;
    #pragma unroll
    for (int q = 0; q < 16; q++) {
        float4 v = cp[q];
        uint32_t h0, l0, h1, l1;
        cvt_pair(v.x, v.y, h0, l0, c2);
        cvt_pair(v.z, v.w, h1, l1, c2);
        g_Chi[h * 32 + q * 2]     = h0;
        g_Chi[h * 32 + q * 2 + 1] = h1;
        g_Clo[h * 32 + q * 2]     = l0;
        g_Clo[h * 32 + q * 2 + 1] = l1;
    }
    g_cw[h] = make_float2(c2 * LOG2E, W[h]);
}

__global__ void __launch_bounds__(THREADS, 2)
rbf_mma_kernel(const float* __restrict__ X, const float* __restrict__ Bias,
               float* __restrict__ out, int ntiles) {
    extern __shared__ char smem_raw[];
    uint32_t sraw = smem_u32(smem_raw);
    uint32_t sb = (sraw + 1023u) & ~1023u;
    char* sc = smem_raw + (sb - sraw);

    const int tid = threadIdx.x;
    const int warp = tid >> 5, lane = tid & 31;
    const int wm = warp >> 1, wn = warp & 1;          // 4 M-warps x 2 N-warps
    const int g = lane >> 2, qq = lane & 3;
    const float TWO_LOG2E = 2.0f * LOG2E;
    const float b0 = Bias[0];

    float2* cws  = (float2*)(sc + OFF_CW);
    float*  red  = (float*)(sc + OFF_RED);

    // ---- stage centers (one thread per center row), swizzled chunks ----
    {
        const int h = tid;
        const uint4* hp = (const uint4*)g_Chi + h * 8;
        const uint4* lp = (const uint4*)g_Clo + h * 8;
        #pragma unroll
        for (int q = 0; q < 8; q++) {
            int co = ((q ^ (h & 7)) * 16);
            *(uint4*)(sc + OFF_BHI + h * 128 + co) = hp[q];
            *(uint4*)(sc + OFF_BLO + h * 128 + co) = lp[q];
        }
        cws[h] = g_cw[h];
    }

    // ---- tile-invariant B ldmatrix base addresses (kt folds in as XOR of kt<<5) ----
    const int roff = (lane & 7) + ((lane >> 3) & 1) * 8;
    const int s16 = lane >> 4;
    uint32_t aBhi[2], aBlo[2];
    #pragma unroll
    for (int gg = 0; gg < 2; gg++) {
        int n = wn * 32 + gg * 16 + roff;
        uint32_t t16 = (uint32_t)((s16 ^ (n & 7)) * 16);
        aBhi[gg] = sb + OFF_BHI + n * 128 + t16;
        aBlo[gg] = sb + OFF_BLO + n * 128 + t16;
    }
    __syncthreads();

    for (int t = blockIdx.x; t < ntiles; t += gridDim.x) {
        // ---- A fragments straight from gmem: lane loads its own fragment
        //      positions (fp32 pairs), splits to bf16 hi/lo in registers,
        //      and accumulates x^2 in-register (q-group partitions each row).
        uint32_t ahi[2][4][4], alo[2][4][4];
        float x2l[2][2];
        {
            const float* xbase = X + (size_t)t * TILE_M * DK;
            #pragma unroll
            for (int mt = 0; mt < 2; mt++)
                #pragma unroll
                for (int h = 0; h < 2; h++) {
                    const float* p = xbase + (wm * 32 + mt * 16 + g + 8 * h) * DK + qq * 2;
                    float s2 = 0.f;
                    #pragma unroll
                    for (int kt = 0; kt < 4; kt++)
                        #pragma unroll
                        for (int s = 0; s < 2; s++) {
                            float2 v = *(const float2*)(p + 16 * kt + 8 * s);
                            cvt_pair(v.x, v.y, ahi[mt][kt][h + 2 * s],
                                     alo[mt][kt][h + 2 * s], s2);
                        }
                    x2l[mt][h] = s2;
                }
            #pragma unroll
            for (int mt = 0; mt < 2; mt++)
                #pragma unroll
                for (int h = 0; h < 2; h++) {
                    float v = x2l[mt][h];
                    v += __shfl_xor_sync(0xffffffffu, v, 1);
                    v += __shfl_xor_sync(0xffffffffu, v, 2);
                    x2l[mt][h] = v * LOG2E;
                }
        }

        float rowsum[2][2] = {{0.f, 0.f}, {0.f, 0.f}};   // [mt][row-half]

        #pragma unroll 1
        for (int nc = 0; nc < 4; nc++) {                 // N chunks of 64
            const int hbase = nc * 64 + wn * 32;
            const uint32_t bo = (uint32_t)(nc * 64 * 128);   // +64 center rows
            const uint32_t bBh0 = aBhi[0] + bo, bBh1 = aBhi[1] + bo;
            const uint32_t bBl0 = aBlo[0] + bo, bBl1 = aBlo[1] + bo;

            float acc[2][4][4];
            #pragma unroll
            for (int mt = 0; mt < 2; mt++)
                #pragma unroll
                for (int nt = 0; nt < 4; nt++)
                    #pragma unroll
                    for (int k = 0; k < 4; k++) acc[mt][nt][k] = 0.f;

            #pragma unroll
            for (int kt = 0; kt < 4; kt++) {
                const uint32_t kx = (uint32_t)(kt << 5);
                uint32_t bh[2][4], bl[2][4];

                LDSM_X4(bh[0][0], bh[0][1], bh[0][2], bh[0][3], bBh0 ^ kx);
                LDSM_X4(bh[1][0], bh[1][1], bh[1][2], bh[1][3], bBh1 ^ kx);
                #pragma unroll
                for (int mt = 0; mt < 2; mt++)
                    #pragma unroll
                    for (int nt = 0; nt < 4; nt++) {
                        const int gg = nt >> 1, od = nt & 1;
                        mma_bf16(acc[mt][nt], ahi[mt][kt], bh[gg][od], bh[gg][od + 2]);
                    }

                LDSM_X4(bl[0][0], bl[0][1], bl[0][2], bl[0][3], bBl0 ^ kx);
                LDSM_X4(bl[1][0], bl[1][1], bl[1][2], bl[1][3], bBl1 ^ kx);
                #pragma unroll
                for (int mt = 0; mt < 2; mt++)
                    #pragma unroll
                    for (int nt = 0; nt < 4; nt++) {
                        const int gg = nt >> 1, od = nt & 1;
                        mma_bf16(acc[mt][nt], alo[mt][kt], bh[gg][od], bh[gg][od + 2]);
                    }
                #pragma unroll
                for (int mt = 0; mt < 2; mt++)
                    #pragma unroll
                    for (int nt = 0; nt < 4; nt++) {
                        const int gg = nt >> 1, od = nt & 1;
                        mma_bf16(acc[mt][nt], ahi[mt][kt], bl[gg][od], bl[gg][od + 2]);
                    }
            }

            // ---- epilogue for this chunk ----
            #pragma unroll
            for (int mt = 0; mt < 2; mt++) {
                const float nx0 = -x2l[mt][0];
                const float nx1 = -x2l[mt][1];
                #pragma unroll
                for (int nt = 0; nt < 4; nt++) {
                    const int h = hbase + nt * 8 + qq * 2;
                    const float2 cw0 = cws[h];
                    const float2 cw1 = cws[h + 1];
                    float t00 = fminf(fmaf(acc[mt][nt][0], TWO_LOG2E, nx0 - cw0.x), 0.f);
                    float t01 = fminf(fmaf(acc[mt][nt][1], TWO_LOG2E, nx0 - cw1.x), 0.f);
                    float t10 = fminf(fmaf(acc[mt][nt][2], TWO_LOG2E, nx1 - cw0.x), 0.f);
                    float t11 = fminf(fmaf(acc[mt][nt][3], TWO_LOG2E, nx1 - cw1.x), 0.f);
                    rowsum[mt][0] = fmaf(cw0.y, ex2_approx(t00), rowsum[mt][0]);
                    rowsum[mt][0] = fmaf(cw1.y, ex2_approx(t01), rowsum[mt][0]);
                    rowsum[mt][1] = fmaf(cw0.y, ex2_approx(t10), rowsum[mt][1]);
                    rowsum[mt][1] = fmaf(cw1.y, ex2_approx(t11), rowsum[mt][1]);
                }
            }
        }

        // ---- reduce 4 col-lanes, then the 2 N-warps via smem ----
        #pragma unroll
        for (int mt = 0; mt < 2; mt++)
            #pragma unroll
            for (int rg = 0; rg < 2; rg++) {
                float v = rowsum[mt][rg];
                v += __shfl_xor_sync(0xffffffffu, v, 1);
                v += __shfl_xor_sync(0xffffffffu, v, 2);
                if (qq == 0)
                    red[(wm * 32 + mt * 16 + rg * 8 + g) * 2 + wn] = v;
            }
        __syncthreads();
        if (tid < TILE_M)
            out[(size_t)t * TILE_M + tid] = red[tid * 2] + red[tid * 2 + 1] + b0;
        __syncthreads();
    }
}

extern "C" void kernel_launch(void* const* d_in, const int* in_sizes, int n_in,
                              void* d_out, int out_size) {
    const float* X = (const float*)d_in[0];
    const float* C = (const float*)d_in[1];
    const float* w = (const float*)d_in[2];
    const float* b = (const float*)d_in[3];
    float* out = (float*)d_out;

    const int ntiles = in_sizes[0] / (DK * TILE_M);   // 4096
    int dev = 0, sms = 148;
    cudaGetDevice(&dev);
    cudaDeviceGetAttribute(&sms, cudaDevAttrMultiProcessorCount, dev);
    int grid = 2 * sms;
    if (grid > ntiles) grid = ntiles;

    prep_kernel<<<1, HN>>>(C, w);
    cudaFuncSetAttribute(rbf_mma_kernel,
                         cudaFuncAttributeMaxDynamicSharedMemorySize, SMEM_SZ);
    rbf_mma_kernel<<<grid, THREADS, SMEM_SZ>>>(X, b, out, ntiles);
}

// round 12
// speedup vs baseline: 3.0365x; 1.8595x over previous
#include <cuda_runtime.h>
#include <cuda_bf16.h>
#include <cstdint>

#define DK 64
#define HN 256
#define TILE_M 128
#define THREADS 256

// precomputed centers (bf16 packed pairs) + exact c2*log2e + w
__device__ uint32_t g_Chi[HN * DK / 2];
__device__ float    g_c2l[HN];
__device__ float    g_w[HN];

// ---- smem byte offsets from 1024-aligned base ----
#define OFF_BHI 0        // 256x128B bf16 centers, swizzled (32KB)
#define OFF_C2  32768    // float[256]  (c2 * log2e)
#define OFF_W   33792    // float[256]
#define OFF_RED 34816    // float[128][2]
#define SMEM_SZ (35840 + 1024)

#define LOG2E 1.4426950408889634f

static __device__ __forceinline__ uint32_t smem_u32(const void* p) {
    uint32_t a;
    asm("{ .reg .u64 t; cvta.to.shared.u64 t, %1; cvt.u32.u64 %0, t; }" : "=r"(a) : "l"(p));
    return a;
}
static __device__ __forceinline__ float ex2_approx(float x) {
    float r; asm("ex2.approx.f32 %0, %1;" : "=f"(r) : "f"(x)); return r;
}
// pack two fp32 -> bf16x2 (lo = a, hi = b), round-to-nearest
static __device__ __forceinline__ uint32_t cvt_bf16x2(float a, float b) {
    uint32_t d;
    asm("cvt.rn.bf16x2.f32 %0, %1, %2;" : "=r"(d) : "f"(b), "f"(a));
    return d;
}

#define LDSM_X4(r0, r1, r2, r3, addr) \
    asm volatile("ldmatrix.sync.aligned.m8n8.x4.shared.b16 {%0,%1,%2,%3}, [%4];" \
        : "=r"(r0), "=r"(r1), "=r"(r2), "=r"(r3) : "r"(addr))

static __device__ __forceinline__ void mma_bf16(float* c, const uint32_t* a,
                                                uint32_t b0, uint32_t b1) {
    asm volatile(
        "mma.sync.aligned.m16n8k16.row.col.f32.bf16.bf16.f32 "
        "{%0,%1,%2,%3}, {%4,%5,%6,%7}, {%8,%9}, {%0,%1,%2,%3};"
        : "+f"(c[0]), "+f"(c[1]), "+f"(c[2]), "+f"(c[3])
        : "r"(a[0]), "r"(a[1]), "r"(a[2]), "r"(a[3]), "r"(b0), "r"(b1));
}

__global__ void prep_kernel(const float* __restrict__ C, const float* __restrict__ W) {
    const int h = threadIdx.x;              // 256 threads, 1 block
    const float4* cp = (const float4*)(C + h * DK);
    float c2 = 0.f;
    #pragma unroll
    for (int q = 0; q < 16; q++) {
        float4 v = cp[q];
        c2 = fmaf(v.x, v.x, c2); c2 = fmaf(v.y, v.y, c2);
        c2 = fmaf(v.z, v.z, c2); c2 = fmaf(v.w, v.w, c2);
        g_Chi[h * 32 + q * 2]     = cvt_bf16x2(v.x, v.y);
        g_Chi[h * 32 + q * 2 + 1] = cvt_bf16x2(v.z, v.w);
    }
    g_c2l[h] = c2 * LOG2E;
    g_w[h]   = W[h];
}

__global__ void __launch_bounds__(THREADS, 2)
rbf_mma_kernel(const float* __restrict__ X, const float* __restrict__ Bias,
               float* __restrict__ out, int ntiles) {
    extern __shared__ char smem_raw[];
    uint32_t sraw = smem_u32(smem_raw);
    uint32_t sb = (sraw + 1023u) & ~1023u;
    char* sc = smem_raw + (sb - sraw);

    const int tid = threadIdx.x;
    const int warp = tid >> 5, lane = tid & 31;
    const int wm = warp >> 1, wn = warp & 1;          // 4 M-warps x 2 N-warps
    const int g = lane >> 2, qq = lane & 3;
    const float TWO_LOG2E = 2.0f * LOG2E;
    const float b0 = Bias[0];

    float* c2s = (float*)(sc + OFF_C2);
    float* ws  = (float*)(sc + OFF_W);
    float* red = (float*)(sc + OFF_RED);

    // ---- stage centers (one thread per center row), swizzled chunks ----
    {
        const int h = tid;
        const uint4* hp = (const uint4*)g_Chi + h * 8;
        #pragma unroll
        for (int q = 0; q < 8; q++) {
            int co = ((q ^ (h & 7)) * 16);
            *(uint4*)(sc + OFF_BHI + h * 128 + co) = hp[q];
        }
        c2s[h] = g_c2l[h];
        ws[h]  = g_w[h];
    }

    // ---- tile-invariant B ldmatrix base addresses (kt folds in as XOR of kt<<5) ----
    const int roff = (lane & 7) + ((lane >> 3) & 1) * 8;
    const int s16 = lane >> 4;
    uint32_t aBhi[2];
    #pragma unroll
    for (int gg = 0; gg < 2; gg++) {
        int n = wn * 32 + gg * 16 + roff;
        uint32_t t16 = (uint32_t)((s16 ^ (n & 7)) * 16);
        aBhi[gg] = sb + OFF_BHI + n * 128 + t16;
    }
    __syncthreads();

    const int step = gridDim.x;

    for (int t = blockIdx.x; t < ntiles; t += step) {
        // ---- A fragments straight from gmem (bf16 in registers) + in-reg x^2 ----
        uint32_t ahi[2][4][4];
        float x2l[2][2];
        {
            const float* xbase = X + (size_t)t * TILE_M * DK;
            #pragma unroll
            for (int mt = 0; mt < 2; mt++)
                #pragma unroll
                for (int h = 0; h < 2; h++) {
                    const float* p = xbase + (wm * 32 + mt * 16 + g + 8 * h) * DK + qq * 2;
                    float s2 = 0.f;
                    #pragma unroll
                    for (int kt = 0; kt < 4; kt++)
                        #pragma unroll
                        for (int s = 0; s < 2; s++) {
                            float2 v = *(const float2*)(p + 16 * kt + 8 * s);
                            s2 = fmaf(v.x, v.x, s2);
                            s2 = fmaf(v.y, v.y, s2);
                            ahi[mt][kt][h + 2 * s] = cvt_bf16x2(v.x, v.y);
                        }
                    x2l[mt][h] = s2;
                }
            #pragma unroll
            for (int mt = 0; mt < 2; mt++)
                #pragma unroll
                for (int h = 0; h < 2; h++) {
                    float v = x2l[mt][h];
                    v += __shfl_xor_sync(0xffffffffu, v, 1);
                    v += __shfl_xor_sync(0xffffffffu, v, 2);
                    x2l[mt][h] = v * LOG2E;
                }
        }

        // ---- prefetch next tile's X into L2 (one 128B line per thread) ----
        {
            int tn = t + step;
            if (tn < ntiles) {
                const char* pf = (const char*)(X + (size_t)tn * TILE_M * DK) + tid * 128;
                asm volatile("prefetch.global.L2 [%0];" :: "l"(pf));
            }
        }

        float rowsum[2][2] = {{0.f, 0.f}, {0.f, 0.f}};   // [mt][row-half]

        #pragma unroll 1
        for (int nc = 0; nc < 4; nc++) {                 // N chunks of 64
            const int hbase = nc * 64 + wn * 32;
            const uint32_t bo = (uint32_t)(nc * 64 * 128);   // +64 center rows
            const uint32_t b0a = aBhi[0] + bo, b1a = aBhi[1] + bo;

            float acc[2][4][4];
            #pragma unroll
            for (int mt = 0; mt < 2; mt++)
                #pragma unroll
                for (int nt = 0; nt < 4; nt++)
                    #pragma unroll
                    for (int k = 0; k < 4; k++) acc[mt][nt][k] = 0.f;

            #pragma unroll
            for (int kt = 0; kt < 4; kt++) {
                const uint32_t kx = (uint32_t)(kt << 5);
                uint32_t bh[2][4];
                LDSM_X4(bh[0][0], bh[0][1], bh[0][2], bh[0][3], b0a ^ kx);
                LDSM_X4(bh[1][0], bh[1][1], bh[1][2], bh[1][3], b1a ^ kx);
                #pragma unroll
                for (int mt = 0; mt < 2; mt++)
                    #pragma unroll
                    for (int nt = 0; nt < 4; nt++) {
                        const int gg = nt >> 1, od = nt & 1;
                        mma_bf16(acc[mt][nt], ahi[mt][kt], bh[gg][od], bh[gg][od + 2]);
                    }
            }

            // ---- epilogue for this chunk (center constants hoisted over mt) ----
            #pragma unroll
            for (int nt = 0; nt < 4; nt++) {
                const int h = hbase + nt * 8 + qq * 2;
                const float2 c2p = *(const float2*)&c2s[h];
                const float2 wp  = *(const float2*)&ws[h];
                #pragma unroll
                for (int mt = 0; mt < 2; mt++) {
                    const float nx0 = -x2l[mt][0];
                    const float nx1 = -x2l[mt][1];
                    float t00 = fminf(fmaf(acc[mt][nt][0], TWO_LOG2E, nx0 - c2p.x), 0.f);
                    float t01 = fminf(fmaf(acc[mt][nt][1], TWO_LOG2E, nx0 - c2p.y), 0.f);
                    float t10 = fminf(fmaf(acc[mt][nt][2], TWO_LOG2E, nx1 - c2p.x), 0.f);
                    float t11 = fminf(fmaf(acc[mt][nt][3], TWO_LOG2E, nx1 - c2p.y), 0.f);
                    rowsum[mt][0] = fmaf(wp.x, ex2_approx(t00), rowsum[mt][0]);
                    rowsum[mt][0] = fmaf(wp.y, ex2_approx(t01), rowsum[mt][0]);
                    rowsum[mt][1] = fmaf(wp.x, ex2_approx(t10), rowsum[mt][1]);
                    rowsum[mt][1] = fmaf(wp.y, ex2_approx(t11), rowsum[mt][1]);
                }
            }
        }

        // ---- reduce 4 col-lanes, then the 2 N-warps via smem ----
        #pragma unroll
        for (int mt = 0; mt < 2; mt++)
            #pragma unroll
            for (int rg = 0; rg < 2; rg++) {
                float v = rowsum[mt][rg];
                v += __shfl_xor_sync(0xffffffffu, v, 1);
                v += __shfl_xor_sync(0xffffffffu, v, 2);
                if (qq == 0)
                    red[(wm * 32 + mt * 16 + rg * 8 + g) * 2 + wn] = v;
            }
        __syncthreads();
        if (tid < TILE_M)
            out[(size_t)t * TILE_M + tid] = red[tid * 2] + red[tid * 2 + 1] + b0;
        __syncthreads();
    }
}

extern "C" void kernel_launch(void* const* d_in, const int* in_sizes, int n_in,
                              void* d_out, int out_size) {
    const float* X = (const float*)d_in[0];
    const float* C = (const float*)d_in[1];
    const float* w = (const float*)d_in[2];
    const float* b = (const float*)d_in[3];
    float* out = (float*)d_out;

    const int ntiles = in_sizes[0] / (DK * TILE_M);   // 4096
    int dev = 0, sms = 148;
    cudaGetDevice(&dev);
    cudaDeviceGetAttribute(&sms, cudaDevAttrMultiProcessorCount, dev);
    int grid = 2 * sms;
    if (grid > ntiles) grid = ntiles;

    prep_kernel<<<1, HN>>>(C, w);
    cudaFuncSetAttribute(rbf_mma_kernel,
                         cudaFuncAttributeMaxDynamicSharedMemorySize, SMEM_SZ);
    rbf_mma_kernel<<<grid, THREADS, SMEM_SZ>>>(X, b, out, ntiles);
}

// round 15
// speedup vs baseline: 3.3253x; 1.0951x over previous
#include <cuda_runtime.h>
#include <cuda_bf16.h>
#include <cstdint>
#include <math.h>

#define DK 64
#define HN 256
#define TILE_M 128
#define THREADS 256

// precomputed centers (bf16 packed pairs) + per-center {log2|w| - L*c2, sign(w)}
__device__ uint32_t g_Chi[HN * DK / 2];
__device__ float2   g_cw2[HN];

// ---- smem byte offsets from 1024-aligned base ----
#define OFF_BHI 0        // 256x128B bf16 centers, swizzled (32KB)
#define OFF_CW2 32768    // float2[256] {lwc2, sgn}
#define OFF_RED 34816    // float[128][2]
#define OFF_X2P 35840    // float[128]  2^(-L*x2) per row
#define SMEM_SZ (36352 + 1024)

#define LOG2E 1.4426950408889634f

static __device__ __forceinline__ uint32_t smem_u32(const void* p) {
    uint32_t a;
    asm("{ .reg .u64 t; cvta.to.shared.u64 t, %1; cvt.u32.u64 %0, t; }" : "=r"(a) : "l"(p));
    return a;
}
static __device__ __forceinline__ float ex2_approx(float x) {
    float r; asm("ex2.approx.f32 %0, %1;" : "=f"(r) : "f"(x)); return r;
}
// pack two fp32 -> bf16x2 (lo = a, hi = b), round-to-nearest
static __device__ __forceinline__ uint32_t cvt_bf16x2(float a, float b) {
    uint32_t d;
    asm("cvt.rn.bf16x2.f32 %0, %1, %2;" : "=r"(d) : "f"(b), "f"(a));
    return d;
}

#define LDSM_X4(r0, r1, r2, r3, addr) \
    asm volatile("ldmatrix.sync.aligned.m8n8.x4.shared.b16 {%0,%1,%2,%3}, [%4];" \
        : "=r"(r0), "=r"(r1), "=r"(r2), "=r"(r3) : "r"(addr))

static __device__ __forceinline__ void mma_bf16(float* c, const uint32_t* a,
                                                uint32_t b0, uint32_t b1) {
    asm volatile(
        "mma.sync.aligned.m16n8k16.row.col.f32.bf16.bf16.f32 "
        "{%0,%1,%2,%3}, {%4,%5,%6,%7}, {%8,%9}, {%0,%1,%2,%3};"
        : "+f"(c[0]), "+f"(c[1]), "+f"(c[2]), "+f"(c[3])
        : "r"(a[0]), "r"(a[1]), "r"(a[2]), "r"(a[3]), "r"(b0), "r"(b1));
}

__global__ void prep_kernel(const float* __restrict__ C, const float* __restrict__ W) {
    const int h = threadIdx.x;              // 256 threads, 1 block
    const float4* cp = (const float4*)(C + h * DK);
    float c2 = 0.f;
    #pragma unroll
    for (int q = 0; q < 16; q++) {
        float4 v = cp[q];
        c2 = fmaf(v.x, v.x, c2); c2 = fmaf(v.y, v.y, c2);
        c2 = fmaf(v.z, v.z, c2); c2 = fmaf(v.w, v.w, c2);
        g_Chi[h * 32 + q * 2]     = cvt_bf16x2(v.x, v.y);
        g_Chi[h * 32 + q * 2 + 1] = cvt_bf16x2(v.z, v.w);
    }
    float wv = W[h];
    // fold |w| and c^2 into one per-column log2-domain constant; sign separate.
    float lwc2 = log2f(fabsf(wv)) - LOG2E * c2;   // w==0 -> -inf -> ex2 -> 0 (correct)
    g_cw2[h] = make_float2(lwc2, wv >= 0.f ? 1.f : -1.f);
}

__global__ void __launch_bounds__(THREADS, 2)
rbf_mma_kernel(const float* __restrict__ X, const float* __restrict__ Bias,
               float* __restrict__ out, int ntiles) {
    extern __shared__ char smem_raw[];
    uint32_t sraw = smem_u32(smem_raw);
    uint32_t sb = (sraw + 1023u) & ~1023u;
    char* sc = smem_raw + (sb - sraw);

    const int tid = threadIdx.x;
    const int warp = tid >> 5, lane = tid & 31;
    const int wm = warp >> 1, wn = warp & 1;          // 4 M-warps x 2 N-warps
    const int g = lane >> 2, qq = lane & 3;
    const float TWO_LOG2E = 2.0f * LOG2E;
    const float b0 = Bias[0];

    float2* cws2 = (float2*)(sc + OFF_CW2);
    float*  red  = (float*)(sc + OFF_RED);
    float*  x2p  = (float*)(sc + OFF_X2P);

    // ---- stage centers (one thread per center row), swizzled chunks ----
    {
        const int h = tid;
        const uint4* hp = (const uint4*)g_Chi + h * 8;
        #pragma unroll
        for (int q = 0; q < 8; q++) {
            int co = ((q ^ (h & 7)) * 16);
            *(uint4*)(sc + OFF_BHI + h * 128 + co) = hp[q];
        }
        cws2[h] = g_cw2[h];
    }

    // ---- tile-invariant B ldmatrix base addresses (kt folds in as XOR of kt<<5) ----
    const int roff = (lane & 7) + ((lane >> 3) & 1) * 8;
    const int s16 = lane >> 4;
    uint32_t aBhi[2];
    #pragma unroll
    for (int gg = 0; gg < 2; gg++) {
        int n = wn * 32 + gg * 16 + roff;
        uint32_t t16 = (uint32_t)((s16 ^ (n & 7)) * 16);
        aBhi[gg] = sb + OFF_BHI + n * 128 + t16;
    }
    __syncthreads();

    const int step = gridDim.x;

    for (int t = blockIdx.x; t < ntiles; t += step) {
        // ---- A fragments straight from gmem (bf16 in registers) + in-reg x^2 ----
        uint32_t ahi[2][4][4];
        {
            const float* xbase = X + (size_t)t * TILE_M * DK;
            float x2v[2][2];
            #pragma unroll
            for (int mt = 0; mt < 2; mt++)
                #pragma unroll
                for (int h = 0; h < 2; h++) {
                    const float* p = xbase + (wm * 32 + mt * 16 + g + 8 * h) * DK + qq * 2;
                    float s2 = 0.f;
                    #pragma unroll
                    for (int kt = 0; kt < 4; kt++)
                        #pragma unroll
                        for (int s = 0; s < 2; s++) {
                            float2 v = *(const float2*)(p + 16 * kt + 8 * s);
                            s2 = fmaf(v.x, v.x, s2);
                            s2 = fmaf(v.y, v.y, s2);
                            ahi[mt][kt][h + 2 * s] = cvt_bf16x2(v.x, v.y);
                        }
                    x2v[mt][h] = s2;
                }
            #pragma unroll
            for (int mt = 0; mt < 2; mt++)
                #pragma unroll
                for (int h = 0; h < 2; h++) {
                    float v = x2v[mt][h];
                    v += __shfl_xor_sync(0xffffffffu, v, 1);
                    v += __shfl_xor_sync(0xffffffffu, v, 2);
                    // per-row factor 2^(-L*x2), stored once; x2 regs die here
                    if (qq == 0)
                        x2p[wm * 32 + mt * 16 + 8 * h + g] = ex2_approx(v * (-LOG2E));
                }
        }

        // ---- prefetch next tile's X into L2 (one 128B line per thread) ----
        {
            int tn = t + step;
            if (tn < ntiles) {
                const char* pf = (const char*)(X + (size_t)tn * TILE_M * DK) + tid * 128;
                asm volatile("prefetch.global.L2 [%0];" :: "l"(pf));
            }
        }

        float rowsum[2][2] = {{0.f, 0.f}, {0.f, 0.f}};   // [mt][row-half]

        #pragma unroll 1
        for (int nc = 0; nc < 4; nc++) {                 // N chunks of 64
            const int hbase = nc * 64 + wn * 32;
            const uint32_t bo = (uint32_t)(nc * 64 * 128);   // +64 center rows
            const uint32_t b0a = aBhi[0] + bo, b1a = aBhi[1] + bo;

            float acc[2][4][4];
            #pragma unroll
            for (int mt = 0; mt < 2; mt++)
                #pragma unroll
                for (int nt = 0; nt < 4; nt++)
                    #pragma unroll
                    for (int k = 0; k < 4; k++) acc[mt][nt][k] = 0.f;

            #pragma unroll
            for (int kt = 0; kt < 4; kt++) {
                const uint32_t kx = (uint32_t)(kt << 5);
                uint32_t bh[2][4];
                LDSM_X4(bh[0][0], bh[0][1], bh[0][2], bh[0][3], b0a ^ kx);
                LDSM_X4(bh[1][0], bh[1][1], bh[1][2], bh[1][3], b1a ^ kx);
                #pragma unroll
                for (int mt = 0; mt < 2; mt++)
                    #pragma unroll
                    for (int nt = 0; nt < 4; nt++) {
                        const int gg = nt >> 1, od = nt & 1;
                        mma_bf16(acc[mt][nt], ahi[mt][kt], bh[gg][od], bh[gg][od + 2]);
                    }
            }

            // ---- epilogue: 3 slots per value (FFMA-imm, MUFU, FFMA) ----
            #pragma unroll
            for (int nt = 0; nt < 4; nt++) {
                const int h = hbase + nt * 8 + qq * 2;
                const float4 cc = *(const float4*)&cws2[h];  // lwc2_0, sgn0, lwc2_1, sgn1
                #pragma unroll
                for (int mt = 0; mt < 2; mt++) {
                    float t00 = fmaf(acc[mt][nt][0], TWO_LOG2E, cc.x);
                    float t01 = fmaf(acc[mt][nt][1], TWO_LOG2E, cc.z);
                    float t10 = fmaf(acc[mt][nt][2], TWO_LOG2E, cc.x);
                    float t11 = fmaf(acc[mt][nt][3], TWO_LOG2E, cc.z);
                    rowsum[mt][0] = fmaf(cc.y, ex2_approx(t00), rowsum[mt][0]);
                    rowsum[mt][0] = fmaf(cc.w, ex2_approx(t01), rowsum[mt][0]);
                    rowsum[mt][1] = fmaf(cc.y, ex2_approx(t10), rowsum[mt][1]);
                    rowsum[mt][1] = fmaf(cc.w, ex2_approx(t11), rowsum[mt][1]);
                }
            }
        }

        // ---- reduce 4 col-lanes, then the 2 N-warps via smem ----
        #pragma unroll
        for (int mt = 0; mt < 2; mt++)
            #pragma unroll
            for (int rg = 0; rg < 2; rg++) {
                float v = rowsum[mt][rg];
                v += __shfl_xor_sync(0xffffffffu, v, 1);
                v += __shfl_xor_sync(0xffffffffu, v, 2);
                if (qq == 0)
                    red[(wm * 32 + mt * 16 + rg * 8 + g) * 2 + wn] = v;
            }
        __syncthreads();
        if (tid < TILE_M)
            out[(size_t)t * TILE_M + tid] =
                fmaf(red[tid * 2] + red[tid * 2 + 1], x2p[tid], b0);
        __syncthreads();
    }
}

extern "C" void kernel_launch(void* const* d_in, const int* in_sizes, int n_in,
                              void* d_out, int out_size) {
    const float* X = (const float*)d_in[0];
    const float* C = (const float*)d_in[1];
    const float* w = (const float*)d_in[2];
    const float* b = (const float*)d_in[3];
    float* out = (float*)d_out;

    const int ntiles = in_sizes[0] / (DK * TILE_M);   // 4096
    int dev = 0, sms = 148;
    cudaGetDevice(&dev);
    cudaDeviceGetAttribute(&sms, cudaDevAttrMultiProcessorCount, dev);
    int grid = 2 * sms;
    if (grid > ntiles) grid = ntiles;

    prep_kernel<<<1, HN>>>(C, w);
    cudaFuncSetAttribute(rbf_mma_kernel,
                         cudaFuncAttributeMaxDynamicSharedMemorySize, SMEM_SZ);
    rbf_mma_kernel<<<grid, THREADS, SMEM_SZ>>>(X, b, out, ntiles);
}

// round 16
// speedup vs baseline: 3.5366x; 1.0635x over previous
#include <cuda_runtime.h>
#include <cuda_bf16.h>
#include <cstdint>
#include <math.h>

#define DK 64
#define HN 256
#define TILE_M 128
#define THREADS 256

// precomputed centers (bf16 packed pairs) + per-center {log2|w| - L*c2, sign(w)}
__device__ uint32_t g_Chi[HN * DK / 2];
__device__ float2   g_cw2[HN];

// ---- smem byte offsets from 1024-aligned base ----
#define OFF_BHI 0        // 256x128B bf16 centers, swizzled (32KB)
#define OFF_CW2 32768    // float2[256] {lwc2, sgn}
#define SMEM_SZ (34816 + 1024)

#define LOG2E 1.4426950408889634f

static __device__ __forceinline__ uint32_t smem_u32(const void* p) {
    uint32_t a;
    asm("{ .reg .u64 t; cvta.to.shared.u64 t, %1; cvt.u32.u64 %0, t; }" : "=r"(a) : "l"(p));
    return a;
}
static __device__ __forceinline__ float ex2_approx(float x) {
    float r; asm("ex2.approx.f32 %0, %1;" : "=f"(r) : "f"(x)); return r;
}
// pack two fp32 -> bf16x2 (lo = a, hi = b), round-to-nearest
static __device__ __forceinline__ uint32_t cvt_bf16x2(float a, float b) {
    uint32_t d;
    asm("cvt.rn.bf16x2.f32 %0, %1, %2;" : "=r"(d) : "f"(b), "f"(a));
    return d;
}

#define LDSM_X4(r0, r1, r2, r3, addr) \
    asm volatile("ldmatrix.sync.aligned.m8n8.x4.shared.b16 {%0,%1,%2,%3}, [%4];" \
        : "=r"(r0), "=r"(r1), "=r"(r2), "=r"(r3) : "r"(addr))

static __device__ __forceinline__ void mma_bf16(float* c, const uint32_t* a,
                                                uint32_t b0, uint32_t b1) {
    asm volatile(
        "mma.sync.aligned.m16n8k16.row.col.f32.bf16.bf16.f32 "
        "{%0,%1,%2,%3}, {%4,%5,%6,%7}, {%8,%9}, {%0,%1,%2,%3};"
        : "+f"(c[0]), "+f"(c[1]), "+f"(c[2]), "+f"(c[3])
        : "r"(a[0]), "r"(a[1]), "r"(a[2]), "r"(a[3]), "r"(b0), "r"(b1));
}

__global__ void prep_kernel(const float* __restrict__ C, const float* __restrict__ W) {
    const int h = threadIdx.x;              // 256 threads, 1 block
    const float4* cp = (const float4*)(C + h * DK);
    float c2 = 0.f;
    #pragma unroll
    for (int q = 0; q < 16; q++) {
        float4 v = cp[q];
        c2 = fmaf(v.x, v.x, c2); c2 = fmaf(v.y, v.y, c2);
        c2 = fmaf(v.z, v.z, c2); c2 = fmaf(v.w, v.w, c2);
        g_Chi[h * 32 + q * 2]     = cvt_bf16x2(v.x, v.y);
        g_Chi[h * 32 + q * 2 + 1] = cvt_bf16x2(v.z, v.w);
    }
    float wv = W[h];
    // fold |w| and c^2 into one per-column log2-domain constant; sign separate.
    float lwc2 = log2f(fabsf(wv)) - LOG2E * c2;   // w==0 -> -inf -> ex2 -> 0 (correct)
    g_cw2[h] = make_float2(lwc2, wv >= 0.f ? 1.f : -1.f);
}

__global__ void __launch_bounds__(THREADS, 2)
rbf_mma_kernel(const float* __restrict__ X, const float* __restrict__ Bias,
               float* __restrict__ out, int ntiles) {
    extern __shared__ char smem_raw[];
    uint32_t sraw = smem_u32(smem_raw);
    uint32_t sb = (sraw + 1023u) & ~1023u;
    char* sc = smem_raw + (sb - sraw);

    const int tid = threadIdx.x;
    const int warp = tid >> 5, lane = tid & 31;
    const int wm = warp >> 1, wn = warp & 1;          // 4 M-warps x 2 N-warps
    const int g = lane >> 2, qq = lane & 3;
    const int stag = warp & 3;                        // per-warp nc stagger
    const float TWO_LOG2E = 2.0f * LOG2E;
    const float bterm = (wn == 0) ? Bias[0] : 0.f;    // bias added once per row

    float2* cws2 = (float2*)(sc + OFF_CW2);

    // ---- stage centers (one thread per center row), swizzled chunks ----
    {
        const int h = tid;
        const uint4* hp = (const uint4*)g_Chi + h * 8;
        #pragma unroll
        for (int q = 0; q < 8; q++) {
            int co = ((q ^ (h & 7)) * 16);
            *(uint4*)(sc + OFF_BHI + h * 128 + co) = hp[q];
        }
        cws2[h] = g_cw2[h];
    }

    // ---- tile-invariant B ldmatrix base addresses (kt folds in as XOR of kt<<5) ----
    const int roff = (lane & 7) + ((lane >> 3) & 1) * 8;
    const int s16 = lane >> 4;
    uint32_t aBhi[2];
    #pragma unroll
    for (int gg = 0; gg < 2; gg++) {
        int n = wn * 32 + gg * 16 + roff;
        uint32_t t16 = (uint32_t)((s16 ^ (n & 7)) * 16);
        aBhi[gg] = sb + OFF_BHI + n * 128 + t16;
    }
    __syncthreads();   // centers visible; NO barriers inside the tile loop

    const int step = gridDim.x;

    for (int t = blockIdx.x; t < ntiles; t += step) {
        // ---- A fragments straight from gmem (bf16 in registers) + in-reg
        //      per-row factor 2^(-L*x2) (kept in registers; no smem) ----
        uint32_t ahi[2][4][4];
        float x2p[2][2];
        {
            const float* xbase = X + (size_t)t * TILE_M * DK;
            #pragma unroll
            for (int mt = 0; mt < 2; mt++)
                #pragma unroll
                for (int h = 0; h < 2; h++) {
                    const float* p = xbase + (wm * 32 + mt * 16 + g + 8 * h) * DK + qq * 2;
                    float s2 = 0.f;
                    #pragma unroll
                    for (int kt = 0; kt < 4; kt++)
                        #pragma unroll
                        for (int s = 0; s < 2; s++) {
                            float2 v = *(const float2*)(p + 16 * kt + 8 * s);
                            s2 = fmaf(v.x, v.x, s2);
                            s2 = fmaf(v.y, v.y, s2);
                            ahi[mt][kt][h + 2 * s] = cvt_bf16x2(v.x, v.y);
                        }
                    x2p[mt][h] = s2;
                }
            #pragma unroll
            for (int mt = 0; mt < 2; mt++)
                #pragma unroll
                for (int h = 0; h < 2; h++) {
                    float v = x2p[mt][h];
                    v += __shfl_xor_sync(0xffffffffu, v, 1);
                    v += __shfl_xor_sync(0xffffffffu, v, 2);
                    x2p[mt][h] = ex2_approx(v * (-LOG2E));
                }
        }

        // ---- prefetch next tile's X into L2 (one 128B line per thread) ----
        {
            int tn = t + step;
            if (tn < ntiles) {
                const char* pf = (const char*)(X + (size_t)tn * TILE_M * DK) + tid * 128;
                asm volatile("prefetch.global.L2 [%0];" :: "l"(pf));
            }
        }

        float rowsum[2][2] = {{0.f, 0.f}, {0.f, 0.f}};   // [mt][row-half]

        #pragma unroll 1
        for (int nci = 0; nci < 4; nci++) {              // N chunks of 64, staggered
            const int nc = (nci + stag) & 3;
            const int hbase = nc * 64 + wn * 32;
            const uint32_t bo = (uint32_t)(nc * 64 * 128);   // +64 center rows
            const uint32_t b0a = aBhi[0] + bo, b1a = aBhi[1] + bo;

            float acc[2][4][4];
            #pragma unroll
            for (int mt = 0; mt < 2; mt++)
                #pragma unroll
                for (int nt = 0; nt < 4; nt++)
                    #pragma unroll
                    for (int k = 0; k < 4; k++) acc[mt][nt][k] = 0.f;

            #pragma unroll
            for (int kt = 0; kt < 4; kt++) {
                const uint32_t kx = (uint32_t)(kt << 5);
                uint32_t bh[2][4];
                LDSM_X4(bh[0][0], bh[0][1], bh[0][2], bh[0][3], b0a ^ kx);
                LDSM_X4(bh[1][0], bh[1][1], bh[1][2], bh[1][3], b1a ^ kx);
                #pragma unroll
                for (int mt = 0; mt < 2; mt++)
                    #pragma unroll
                    for (int nt = 0; nt < 4; nt++) {
                        const int gg = nt >> 1, od = nt & 1;
                        mma_bf16(acc[mt][nt], ahi[mt][kt], bh[gg][od], bh[gg][od + 2]);
                    }
            }

            // ---- epilogue: 3 slots per value (FFMA-imm, MUFU, FFMA) ----
            #pragma unroll
            for (int nt = 0; nt < 4; nt++) {
                const int h = hbase + nt * 8 + qq * 2;
                const float4 cc = *(const float4*)&cws2[h];  // lwc2_0, sgn0, lwc2_1, sgn1
                #pragma unroll
                for (int mt = 0; mt < 2; mt++) {
                    float t00 = fmaf(acc[mt][nt][0], TWO_LOG2E, cc.x);
                    float t01 = fmaf(acc[mt][nt][1], TWO_LOG2E, cc.z);
                    float t10 = fmaf(acc[mt][nt][2], TWO_LOG2E, cc.x);
                    float t11 = fmaf(acc[mt][nt][3], TWO_LOG2E, cc.z);
                    rowsum[mt][0] = fmaf(cc.y, ex2_approx(t00), rowsum[mt][0]);
                    rowsum[mt][0] = fmaf(cc.w, ex2_approx(t01), rowsum[mt][0]);
                    rowsum[mt][1] = fmaf(cc.y, ex2_approx(t10), rowsum[mt][1]);
                    rowsum[mt][1] = fmaf(cc.w, ex2_approx(t11), rowsum[mt][1]);
                }
            }
        }

        // ---- qq-lane reduce, then DIRECT atomic writeback (no barriers).
        //      Each out row receives exactly 2 float adds (wn=0, wn=1):
        //      commutative -> bit-deterministic across replays.
        float* obase = out + (size_t)t * TILE_M;
        #pragma unroll
        for (int mt = 0; mt < 2; mt++)
            #pragma unroll
            for (int rg = 0; rg < 2; rg++) {
                float v = rowsum[mt][rg];
                v += __shfl_xor_sync(0xffffffffu, v, 1);
                v += __shfl_xor_sync(0xffffffffu, v, 2);
                if (qq == 0)
                    atomicAdd(obase + wm * 32 + mt * 16 + rg * 8 + g,
                              fmaf(v, x2p[mt][rg], bterm));
            }
    }
}

extern "C" void kernel_launch(void* const* d_in, const int* in_sizes, int n_in,
                              void* d_out, int out_size) {
    const float* X = (const float*)d_in[0];
    const float* C = (const float*)d_in[1];
    const float* w = (const float*)d_in[2];
    const float* b = (const float*)d_in[3];
    float* out = (float*)d_out;

    const int ntiles = in_sizes[0] / (DK * TILE_M);   // 4096
    int dev = 0, sms = 148;
    cudaGetDevice(&dev);
    cudaDeviceGetAttribute(&sms, cudaDevAttrMultiProcessorCount, dev);
    int grid = 2 * sms;
    if (grid > ntiles) grid = ntiles;

    cudaMemsetAsync(out, 0, (size_t)out_size * sizeof(float));
    prep_kernel<<<1, HN>>>(C, w);
    cudaFuncSetAttribute(rbf_mma_kernel,
                         cudaFuncAttributeMaxDynamicSharedMemorySize, SMEM_SZ);
    rbf_mma_kernel<<<grid, THREADS, SMEM_SZ>>>(X, b, out, ntiles);
}

// round 17
// speedup vs baseline: 4.1017x; 1.1598x over previous
#include <cuda_runtime.h>
#include <cuda_bf16.h>
#include <cstdint>
#include <math.h>

#define DK 64
#define HN 256
#define THREADS 256

__device__ unsigned g_ctr;

// ---- smem byte offsets from 1024-aligned base ----
#define OFF_BHI 0        // 256x128B bf16 centers, swizzled (32KB)
#define OFF_CW2 32768    // float2[256] {lwc2, sgn}
#define SMEM_SZ (34816 + 1024)

#define LOG2E 1.4426950408889634f

static __device__ __forceinline__ uint32_t smem_u32(const void* p) {
    uint32_t a;
    asm("{ .reg .u64 t; cvta.to.shared.u64 t, %1; cvt.u32.u64 %0, t; }" : "=r"(a) : "l"(p));
    return a;
}
static __device__ __forceinline__ float ex2_approx(float x) {
    float r; asm("ex2.approx.f32 %0, %1;" : "=f"(r) : "f"(x)); return r;
}
// pack two fp32 -> bf16x2 (lo = a, hi = b), round-to-nearest
static __device__ __forceinline__ uint32_t cvt_bf16x2(float a, float b) {
    uint32_t d;
    asm("cvt.rn.bf16x2.f32 %0, %1, %2;" : "=r"(d) : "f"(b), "f"(a));
    return d;
}

#define LDSM_X4(r0, r1, r2, r3, addr) \
    asm volatile("ldmatrix.sync.aligned.m8n8.x4.shared.b16 {%0,%1,%2,%3}, [%4];" \
        : "=r"(r0), "=r"(r1), "=r"(r2), "=r"(r3) : "r"(addr))

static __device__ __forceinline__ void mma_bf16(float* c, const uint32_t* a,
                                                uint32_t b0, uint32_t b1) {
    asm volatile(
        "mma.sync.aligned.m16n8k16.row.col.f32.bf16.bf16.f32 "
        "{%0,%1,%2,%3}, {%4,%5,%6,%7}, {%8,%9}, {%0,%1,%2,%3};"
        : "+f"(c[0]), "+f"(c[1]), "+f"(c[2]), "+f"(c[3])
        : "r"(a[0]), "r"(a[1]), "r"(a[2]), "r"(a[3]), "r"(b0), "r"(b1));
}

__global__ void __launch_bounds__(THREADS, 2)
rbf_mma_kernel(const float* __restrict__ X, const float* __restrict__ C,
               const float* __restrict__ W, const float* __restrict__ Bias,
               float* __restrict__ out, int nunits) {
    extern __shared__ char smem_raw[];
    uint32_t sraw = smem_u32(smem_raw);
    uint32_t sb = (sraw + 1023u) & ~1023u;
    char* sc = smem_raw + (sb - sraw);

    const int tid = threadIdx.x;
    const int lane = tid & 31;
    const int warp = tid >> 5;
    const int g = lane >> 2, qq = lane & 3;
    const int stag = warp & 3;
    const float TWO_LOG2E = 2.0f * LOG2E;
    const float b0 = Bias[0];

    float2* cws2 = (float2*)(sc + OFF_CW2);

    // ---- inline center prep: one thread per center row, straight from C/W ----
    {
        const int h = tid;
        const float4* cp = (const float4*)(C + h * DK);
        float c2 = 0.f;
        #pragma unroll
        for (int q = 0; q < 8; q++) {
            float4 v0 = cp[2 * q], v1 = cp[2 * q + 1];
            c2 = fmaf(v0.x, v0.x, c2); c2 = fmaf(v0.y, v0.y, c2);
            c2 = fmaf(v0.z, v0.z, c2); c2 = fmaf(v0.w, v0.w, c2);
            c2 = fmaf(v1.x, v1.x, c2); c2 = fmaf(v1.y, v1.y, c2);
            c2 = fmaf(v1.z, v1.z, c2); c2 = fmaf(v1.w, v1.w, c2);
            uint4 pk = make_uint4(cvt_bf16x2(v0.x, v0.y), cvt_bf16x2(v0.z, v0.w),
                                  cvt_bf16x2(v1.x, v1.y), cvt_bf16x2(v1.z, v1.w));
            *(uint4*)(sc + OFF_BHI + h * 128 + ((q ^ (h & 7)) * 16)) = pk;
        }
        float wv = W[h];
        float lwc2 = log2f(fabsf(wv)) - LOG2E * c2;   // w==0 -> -inf -> ex2 -> 0
        cws2[h] = make_float2(lwc2, wv >= 0.f ? 1.f : -1.f);
    }

    // ---- tile-invariant B ldmatrix bases (kt folds in as XOR of kt<<5) ----
    const int roff = (lane & 7) + ((lane >> 3) & 1) * 8;
    const int s16 = lane >> 4;
    uint32_t aBhi[2];
    #pragma unroll
    for (int gg = 0; gg < 2; gg++) {
        int n = gg * 16 + roff;
        uint32_t t16 = (uint32_t)((s16 ^ (n & 7)) * 16);
        aBhi[gg] = sb + OFF_BHI + n * 128 + t16;
    }
    __syncthreads();   // centers visible; warps free-run from here

    // ---- warp-autonomous unit loop (unit = 32 rows x all 256 cols) ----
    unsigned u;
    if (lane == 0) u = atomicAdd(&g_ctr, 1u);
    u = __shfl_sync(0xffffffffu, u, 0);

    while (u < (unsigned)nunits) {
        // fetch NEXT unit early (hides atomic latency; drives prefetch)
        unsigned un;
        if (lane == 0) un = atomicAdd(&g_ctr, 1u);
        un = __shfl_sync(0xffffffffu, un, 0);

        // ---- stage A fragments from gmem + per-row 2^(-L*x2) in regs ----
        uint32_t ahi[2][4][4];
        float x2p[2][2];
        {
            const float* xbase = X + (size_t)u * 32 * DK;
            #pragma unroll
            for (int mt = 0; mt < 2; mt++)
                #pragma unroll
                for (int h = 0; h < 2; h++) {
                    const float* p = xbase + (mt * 16 + g + 8 * h) * DK + qq * 2;
                    float s2 = 0.f;
                    #pragma unroll
                    for (int kt = 0; kt < 4; kt++)
                        #pragma unroll
                        for (int s = 0; s < 2; s++) {
                            float2 v = *(const float2*)(p + 16 * kt + 8 * s);
                            s2 = fmaf(v.x, v.x, s2);
                            s2 = fmaf(v.y, v.y, s2);
                            ahi[mt][kt][h + 2 * s] = cvt_bf16x2(v.x, v.y);
                        }
                    x2p[mt][h] = s2;
                }
            #pragma unroll
            for (int mt = 0; mt < 2; mt++)
                #pragma unroll
                for (int h = 0; h < 2; h++) {
                    float v = x2p[mt][h];
                    v += __shfl_xor_sync(0xffffffffu, v, 1);
                    v += __shfl_xor_sync(0xffffffffu, v, 2);
                    x2p[mt][h] = ex2_approx(v * (-LOG2E));
                }
        }

        // ---- prefetch next unit's X into L2 (2x128B per lane = 8KB) ----
        if (un < (unsigned)nunits) {
            const char* pf = (const char*)(X + (size_t)un * 32 * DK) + lane * 256;
            asm volatile("prefetch.global.L2 [%0];" :: "l"(pf));
            asm volatile("prefetch.global.L2 [%0];" :: "l"(pf + 128));
        }

        float rowsum[2][2] = {{0.f, 0.f}, {0.f, 0.f}};   // [mt][row-half]

        #pragma unroll 1
        for (int nci = 0; nci < 4; nci++) {              // N chunks of 64
            const int nc = (nci + stag) & 3;
            #pragma unroll
            for (int half = 0; half < 2; half++) {       // 32-col sub-blocks
                const int hbase = nc * 64 + half * 32;
                const uint32_t bo = (uint32_t)(hbase * 128);
                const uint32_t b0a = aBhi[0] + bo, b1a = aBhi[1] + bo;

                float acc[2][4][4];
                #pragma unroll
                for (int mt = 0; mt < 2; mt++)
                    #pragma unroll
                    for (int nt = 0; nt < 4; nt++)
                        #pragma unroll
                        for (int k = 0; k < 4; k++) acc[mt][nt][k] = 0.f;

                #pragma unroll
                for (int kt = 0; kt < 4; kt++) {
                    const uint32_t kx = (uint32_t)(kt << 5);
                    uint32_t bh[2][4];
                    LDSM_X4(bh[0][0], bh[0][1], bh[0][2], bh[0][3], b0a ^ kx);
                    LDSM_X4(bh[1][0], bh[1][1], bh[1][2], bh[1][3], b1a ^ kx);
                    #pragma unroll
                    for (int mt = 0; mt < 2; mt++)
                        #pragma unroll
                        for (int nt = 0; nt < 4; nt++) {
                            const int gg = nt >> 1, od = nt & 1;
                            mma_bf16(acc[mt][nt], ahi[mt][kt], bh[gg][od], bh[gg][od + 2]);
                        }
                }

                // ---- epilogue: 3 slots per value (FFMA, MUFU, FFMA) ----
                #pragma unroll
                for (int nt = 0; nt < 4; nt++) {
                    const int h = hbase + nt * 8 + qq * 2;
                    const float4 cc = *(const float4*)&cws2[h];
                    #pragma unroll
                    for (int mt = 0; mt < 2; mt++) {
                        float t00 = fmaf(acc[mt][nt][0], TWO_LOG2E, cc.x);
                        float t01 = fmaf(acc[mt][nt][1], TWO_LOG2E, cc.z);
                        float t10 = fmaf(acc[mt][nt][2], TWO_LOG2E, cc.x);
                        float t11 = fmaf(acc[mt][nt][3], TWO_LOG2E, cc.z);
                        rowsum[mt][0] = fmaf(cc.y, ex2_approx(t00), rowsum[mt][0]);
                        rowsum[mt][0] = fmaf(cc.w, ex2_approx(t01), rowsum[mt][0]);
                        rowsum[mt][1] = fmaf(cc.y, ex2_approx(t10), rowsum[mt][1]);
                        rowsum[mt][1] = fmaf(cc.w, ex2_approx(t11), rowsum[mt][1]);
                    }
                }
            }
        }

        // ---- qq-lane reduce, then direct store (each row owned by this warp) ----
        float* obase = out + (size_t)u * 32;
        #pragma unroll
        for (int mt = 0; mt < 2; mt++)
            #pragma unroll
            for (int rg = 0; rg < 2; rg++) {
                float v = rowsum[mt][rg];
                v += __shfl_xor_sync(0xffffffffu, v, 1);
                v += __shfl_xor_sync(0xffffffffu, v, 2);
                if (qq == 0)
                    obase[mt * 16 + rg * 8 + g] = fmaf(v, x2p[mt][rg], b0);
            }

        u = un;
    }
}

extern "C" void kernel_launch(void* const* d_in, const int* in_sizes, int n_in,
                              void* d_out, int out_size) {
    const float* X = (const float*)d_in[0];
    const float* C = (const float*)d_in[1];
    const float* w = (const float*)d_in[2];
    const float* b = (const float*)d_in[3];
    float* out = (float*)d_out;

    const int nunits = in_sizes[0] / (DK * 32);   // 16384 units of 32 rows
    int dev = 0, sms = 148;
    cudaGetDevice(&dev);
    cudaDeviceGetAttribute(&sms, cudaDevAttrMultiProcessorCount, dev);
    int grid = 2 * sms;

    void* ctr_addr = nullptr;
    cudaGetSymbolAddress(&ctr_addr, g_ctr);
    cudaMemsetAsync(ctr_addr, 0, sizeof(unsigned));

    cudaFuncSetAttribute(rbf_mma_kernel,
                         cudaFuncAttributeMaxDynamicSharedMemorySize, SMEM_SZ);
    rbf_mma_kernel<<<grid, THREADS, SMEM_SZ>>>(X, C, w, b, out, nunits);
}